// round 2
// baseline (speedup 1.0000x reference)
#include <cuda_runtime.h>
#include <cstdint>
#include <float.h>

#define BATCHN 256
#define DDIM   512
#define HDIM   2048
#define SLOTSN 32768
#define CCAP   512
#define CDELTA 12.0f
#define PART_ELEMS (32*256*512)

// ---------------- scratch (static device globals; no allocation) ----------------
__device__ float g_K[BATCHN*DDIM];
__device__ float g_V[BATCHN*DDIM];
__device__ float g_G[BATCHN*BATCHN];
__device__ float g_base[(size_t)BATCHN*SLOTSN];   // 32 MB raw scores
__device__ float g_E[(size_t)BATCHN*SLOTSN];      // 32 MB exp(scores - m)
__device__ float g_m[BATCHN];
__device__ float g_Z0[BATCHN];
__device__ float g_Zc[BATCHN];
__device__ float g_R0[BATCHN*DDIM];
__device__ float g_Rc[BATCHN*DDIM];
__device__ float g_cand_val[BATCHN*CCAP];
__device__ int   g_cand_slot[BATCHN*CCAP];
__device__ int   g_cand_cnt[BATCHN];
__device__ int   g_slots[BATCHN];
__device__ int   g_nxt[BATCHN];
__device__ float g_Ccat[BATCHN*2*BATCHN];
__device__ float g_Vcat[2*BATCHN*DDIM];
__device__ float g_Merged[BATCHN*2*DDIM];
__device__ float g_Hidden[BATCHN*HDIM];
__device__ float g_Part[PART_ELEMS];

// ---------------- generic 128x128x8 fp32 tiled GEMM, split-K via blockIdx.z ----
// BT=true : C[m,n] = sum_k A[m,k] * B[n,k]   (B row-major [N,Kd])
// BT=false: C[m,n] = sum_k A[m,k] * B[k,n]   (B row-major [Kd,N])
// Output goes to C + z*M*N (partial per split; split==1 -> direct).
template<bool BT>
__global__ __launch_bounds__(256, 2) void gemm_kernel(
    const float* __restrict__ A, const float* __restrict__ B, float* __restrict__ C,
    int M, int N, int Kd, int kChunk)
{
    __shared__ float As[8][128];
    __shared__ float Bs[8][128];
    const int tid = threadIdx.x;
    const int tx = tid & 15, ty = tid >> 4;
    const int bn = blockIdx.x, bm = blockIdx.y, bz = blockIdx.z;
    const int k0 = bz * kChunk;

    const int ar = tid >> 1, aq = (tid & 1) << 2;
    const float* Arow = A + (size_t)(bm*128 + ar)*Kd + aq;
    const float* Brow;
    if (BT) Brow = B + (size_t)(bn*128 + ar)*Kd + aq;
    else    Brow = B + (size_t)(k0 + (tid >> 5))*N + bn*128 + ((tid & 31) << 2);

    float acc[8][8];
    #pragma unroll
    for (int r = 0; r < 8; r++)
        #pragma unroll
        for (int c = 0; c < 8; c++) acc[r][c] = 0.f;

    for (int k = k0; k < k0 + kChunk; k += 8) {
        float4 av = *(const float4*)(Arow + k);
        As[aq+0][ar] = av.x; As[aq+1][ar] = av.y; As[aq+2][ar] = av.z; As[aq+3][ar] = av.w;
        if (BT) {
            float4 bv = *(const float4*)(Brow + k);
            Bs[aq+0][ar] = bv.x; Bs[aq+1][ar] = bv.y; Bs[aq+2][ar] = bv.z; Bs[aq+3][ar] = bv.w;
        } else {
            float4 bv = *(const float4*)Brow;
            *(float4*)&Bs[tid >> 5][(tid & 31) << 2] = bv;
            Brow += 8 * (size_t)N;
        }
        __syncthreads();
        #pragma unroll
        for (int kk = 0; kk < 8; kk++) {
            float a[8], b[8];
            *(float4*)&a[0] = *(const float4*)&As[kk][ty << 2];
            *(float4*)&a[4] = *(const float4*)&As[kk][64 + (ty << 2)];
            *(float4*)&b[0] = *(const float4*)&Bs[kk][tx << 2];
            *(float4*)&b[4] = *(const float4*)&Bs[kk][64 + (tx << 2)];
            #pragma unroll
            for (int r = 0; r < 8; r++)
                #pragma unroll
                for (int c = 0; c < 8; c++) acc[r][c] += a[r] * b[c];
        }
        __syncthreads();
    }

    float* Cout = C + (size_t)bz * M * N;
    const int mbase = bm*128, nbase = bn*128;
    #pragma unroll
    for (int rh = 0; rh < 2; rh++)
        #pragma unroll
        for (int rr = 0; rr < 4; rr++) {
            int r = rh*4 + rr;
            int m = mbase + rh*64 + (ty << 2) + rr;
            float* crow = Cout + (size_t)m * N + nbase;
            *(float4*)(crow + (tx << 2))      = make_float4(acc[r][0], acc[r][1], acc[r][2], acc[r][3]);
            *(float4*)(crow + 64 + (tx << 2)) = make_float4(acc[r][4], acc[r][5], acc[r][6], acc[r][7]);
        }
}

// sum split partials + optional bias + optional relu
__global__ void reduce_kernel(const float* __restrict__ P, float* __restrict__ C,
                              const float* __restrict__ bias, int MN, int N, int split, int relu)
{
    int idx = blockIdx.x * 256 + threadIdx.x;
    if (idx >= MN) return;
    float s = 0.f;
    for (int z = 0; z < split; z++) s += P[(size_t)z * MN + idx];
    if (bias) s += bias[idx % N];
    if (relu) s = fmaxf(s, 0.f);
    C[idx] = s;
}

__global__ void rowmax_kernel(const float* __restrict__ base, float* __restrict__ m)
{
    int i = blockIdx.x, tid = threadIdx.x;
    const float* row = base + (size_t)i * SLOTSN;
    float mx = -FLT_MAX;
    for (int s = tid; s < SLOTSN; s += 256) mx = fmaxf(mx, row[s]);
    for (int o = 16; o; o >>= 1) mx = fmaxf(mx, __shfl_down_sync(0xffffffffu, mx, o));
    __shared__ float sh[8];
    if ((tid & 31) == 0) sh[tid >> 5] = mx;
    __syncthreads();
    if (tid == 0) { float r = sh[0]; for (int w = 1; w < 8; w++) r = fmaxf(r, sh[w]); m[i] = r; }
}

// E = exp(base - m), Z0 row sums, candidate collection (base >= m - CDELTA)
__global__ void e_kernel(const float* __restrict__ base, const float* __restrict__ m,
                         float* __restrict__ E, float* __restrict__ Z0,
                         float* __restrict__ cval, int* __restrict__ cslot, int* __restrict__ ccnt)
{
    int i = blockIdx.x, tid = threadIdx.x;
    __shared__ int cnt;
    if (tid == 0) cnt = 0;
    __syncthreads();
    float mi = m[i], thr = mi - CDELTA, z = 0.f;
    const float* row = base + (size_t)i * SLOTSN;
    float* erow = E + (size_t)i * SLOTSN;
    for (int s = tid; s < SLOTSN; s += 256) {
        float b = row[s];
        float e = __expf(b - mi);
        erow[s] = e;
        z += e;
        if (b >= thr) {
            int idx = atomicAdd(&cnt, 1);
            if (idx < CCAP) { cval[i*CCAP + idx] = b; cslot[i*CCAP + idx] = s; }
        }
    }
    for (int o = 16; o; o >>= 1) z += __shfl_down_sync(0xffffffffu, z, o);
    __shared__ float sh[8];
    if ((tid & 31) == 0) sh[tid >> 5] = z;
    __syncthreads();
    if (tid == 0) { float r = 0; for (int w = 0; w < 8; w++) r += sh[w]; Z0[i] = r; ccnt[i] = cnt; }
}

__device__ __forceinline__ unsigned long long mk_key(float v, int slot)
{
    unsigned u = __float_as_uint(v);
    u = (u & 0x80000000u) ? ~u : (u | 0x80000000u);
    // tie -> smaller slot wins (matches argmax first-index semantics)
    return ((unsigned long long)u << 32) | (unsigned)(0xFFFFFFFFu - (unsigned)slot);
}

// the only sequential part: the 256-step slot chain
__global__ void seq_kernel(const float* __restrict__ G, const float* __restrict__ m,
                           const float* __restrict__ cval, const int* __restrict__ cslot,
                           const int* __restrict__ ccnt, const float* __restrict__ base,
                           int* __restrict__ slots_out, int* __restrict__ nxt_out)
{
    extern __shared__ short mapw[];           // 32768 x int16 last-writer map
    __shared__ int slots_s[256];
    __shared__ unsigned char alive[256];
    __shared__ short nxt[256];
    __shared__ unsigned long long wred[8];
    int tid = threadIdx.x;
    for (int s = tid; s < SLOTSN; s += 256) mapw[s] = -1;
    alive[tid] = 0; nxt[tid] = 1000;
    __syncthreads();

    for (int i = 0; i < 256; i++) {
        unsigned long long best = 0ull;
        // candidates from live (updated) slots: current score is G[j,i]
        if (tid < i && alive[tid]) best = mk_key(G[i*256 + tid], slots_s[tid]);
        int cnt = ccnt[i];
        bool needfull = (cnt > CCAP);
        bool found = false;
        if (!needfull) {
            for (int c = tid; c < cnt; c += 256) {
                int s = cslot[i*CCAP + c];
                if (mapw[s] < 0) {
                    found = true;
                    unsigned long long k = mk_key(cval[i*CCAP + c], s);
                    if (k > best) best = k;
                }
            }
        }
        // exact fallback: if no non-updated candidate above threshold, scan full row
        if (!__syncthreads_or((int)found) || needfull) {
            const float* row = base + (size_t)i * SLOTSN;
            for (int s = tid; s < SLOTSN; s += 256)
                if (mapw[s] < 0) {
                    unsigned long long k = mk_key(row[s], s);
                    if (k > best) best = k;
                }
        }
        for (int o = 16; o; o >>= 1) {
            unsigned long long k = __shfl_down_sync(0xffffffffu, best, o);
            if (k > best) best = k;
        }
        if ((tid & 31) == 0) wred[tid >> 5] = best;
        __syncthreads();
        if (tid == 0) {
            unsigned long long b = wred[0];
            for (int w = 1; w < 8; w++) if (wred[w] > b) b = wred[w];
            int slot = (int)(0xFFFFFFFFu - (unsigned)(b & 0xFFFFFFFFull));
            int old = mapw[slot];
            if (old >= 0) { alive[old] = 0; nxt[old] = (short)i; }
            mapw[slot] = (short)i;
            alive[i] = 1;
            slots_s[i] = slot;
        }
        __syncthreads();
    }
    slots_out[tid] = slots_s[tid];
    nxt_out[tid] = nxt[tid];
}

// correction coefficient matrix: Ccat = [C1 | -C2], Zc = rowsum(C1 - C2)
__global__ void cbuild_kernel(const float* __restrict__ G, const float* __restrict__ m,
                              const float* __restrict__ E, const int* __restrict__ slots,
                              const int* __restrict__ nxt, float* __restrict__ Ccat,
                              float* __restrict__ Zc)
{
    int i = blockIdx.x, j = threadIdx.x;
    float c1 = 0.f, c2 = 0.f;
    if (j < i && nxt[j] >= i) {                  // step j is the live last-writer of its slot at step i
        c1 = __expf(G[i*256 + j] - m[i]);        // new score of that slot
        c2 = E[(size_t)i * SLOTSN + slots[j]];   // stale contribution to remove
    }
    Ccat[i*512 + j] = c1;
    Ccat[i*512 + 256 + j] = -c2;
    float d = c1 - c2;
    for (int o = 16; o; o >>= 1) d += __shfl_down_sync(0xffffffffu, d, o);
    __shared__ float sh[8];
    if ((j & 31) == 0) sh[j >> 5] = d;
    __syncthreads();
    if (j == 0) { float r = 0; for (int w = 0; w < 8; w++) r += sh[w]; Zc[i] = r; }
}

// Vcat = [V ; mem_vals[slots]]
__global__ void vcat_kernel(const float* __restrict__ V, const float* __restrict__ mv,
                            const int* __restrict__ slots, float* __restrict__ Vcat)
{
    int j = blockIdx.x, d = threadIdx.x;
    if (j < 256) Vcat[(size_t)j*512 + d] = V[j*512 + d];
    else         Vcat[(size_t)j*512 + d] = mv[(size_t)slots[j-256]*512 + d];
}

// Merged = [S | (R0+Rc)/(Z0+Zc)]
__global__ void merged_kernel(const float* __restrict__ S, const float* __restrict__ R0,
                              const float* __restrict__ Rc, const float* __restrict__ Z0,
                              const float* __restrict__ Zc, float* __restrict__ Mg)
{
    int i = blockIdx.x, d = threadIdx.x;
    Mg[i*1024 + d] = S[i*512 + d];
    Mg[i*1024 + 512 + d] = (R0[i*512 + d] + Rc[i*512 + d]) / (Z0[i] + Zc[i]);
}

extern "C" void kernel_launch(void* const* d_in, const int* in_sizes, int n_in,
                              void* d_out, int out_size)
{
    (void)in_sizes; (void)n_in; (void)out_size;
    const float* S  = (const float*)d_in[0];
    const float* MK = (const float*)d_in[1];
    const float* MV = (const float*)d_in[2];
    const float* Wk = (const float*)d_in[3];
    const float* bk = (const float*)d_in[4];
    const float* Wv = (const float*)d_in[5];
    const float* bv = (const float*)d_in[6];
    const float* W1 = (const float*)d_in[7];
    const float* b1 = (const float*)d_in[8];
    const float* W2 = (const float*)d_in[9];
    const float* b2 = (const float*)d_in[10];
    float* out = (float*)d_out;

    float *pK, *pV, *pG, *pBase, *pE, *pm, *pZ0, *pZc, *pR0, *pRc;
    float *pCval, *pCcat, *pVcat, *pMg, *pHid, *pPart;
    int *pCslot, *pCcnt, *pSlots, *pNxt;
    cudaGetSymbolAddress((void**)&pK, g_K);
    cudaGetSymbolAddress((void**)&pV, g_V);
    cudaGetSymbolAddress((void**)&pG, g_G);
    cudaGetSymbolAddress((void**)&pBase, g_base);
    cudaGetSymbolAddress((void**)&pE, g_E);
    cudaGetSymbolAddress((void**)&pm, g_m);
    cudaGetSymbolAddress((void**)&pZ0, g_Z0);
    cudaGetSymbolAddress((void**)&pZc, g_Zc);
    cudaGetSymbolAddress((void**)&pR0, g_R0);
    cudaGetSymbolAddress((void**)&pRc, g_Rc);
    cudaGetSymbolAddress((void**)&pCval, g_cand_val);
    cudaGetSymbolAddress((void**)&pCslot, g_cand_slot);
    cudaGetSymbolAddress((void**)&pCcnt, g_cand_cnt);
    cudaGetSymbolAddress((void**)&pSlots, g_slots);
    cudaGetSymbolAddress((void**)&pNxt, g_nxt);
    cudaGetSymbolAddress((void**)&pCcat, g_Ccat);
    cudaGetSymbolAddress((void**)&pVcat, g_Vcat);
    cudaGetSymbolAddress((void**)&pMg, g_Merged);
    cudaGetSymbolAddress((void**)&pHid, g_Hidden);
    cudaGetSymbolAddress((void**)&pPart, g_Part);

    dim3 thr(256);

    // projections: K = S@Wk^T + bk, V = S@Wv^T + bv
    gemm_kernel<true><<<dim3(4, 2, 8), thr>>>(S, Wk, pPart, 256, 512, 512, 64);
    reduce_kernel<<<512, 256>>>(pPart, pK, bk, 256*512, 512, 8, 0);
    gemm_kernel<true><<<dim3(4, 2, 8), thr>>>(S, Wv, pPart, 256, 512, 512, 64);
    reduce_kernel<<<512, 256>>>(pPart, pV, bv, 256*512, 512, 8, 0);

    // Gram: G = K @ K^T
    gemm_kernel<true><<<dim3(2, 2, 16), thr>>>(pK, pK, pPart, 256, 256, 512, 32);
    reduce_kernel<<<256, 256>>>(pPart, pG, nullptr, 256*256, 256, 16, 0);

    // base scores vs ORIGINAL memory: base = K @ mem_keys^T  (8.6 GFLOP)
    gemm_kernel<true><<<dim3(256, 2, 1), thr>>>(pK, MK, pBase, 256, 32768, 512, 512);
    rowmax_kernel<<<256, 256>>>(pBase, pm);
    e_kernel<<<256, 256>>>(pBase, pm, pE, pZ0, pCval, pCslot, pCcnt);

    // bulk read term: R0 = E @ mem_vals  (8.6 GFLOP, split-K 32)
    gemm_kernel<false><<<dim3(4, 2, 32), thr>>>(pE, MV, pPart, 256, 512, 32768, 1024);
    reduce_kernel<<<512, 256>>>(pPart, pR0, nullptr, 256*512, 512, 32, 0);

    // sequential slot chain (only truly serial part)
    cudaFuncSetAttribute(seq_kernel, cudaFuncAttributeMaxDynamicSharedMemorySize, SLOTSN * 2);
    seq_kernel<<<1, 256, SLOTSN * 2>>>(pG, pm, pCval, pCslot, pCcnt, pBase, pSlots, pNxt);

    // per-step softmax corrections as small GEMM: Rc = Ccat @ Vcat
    cbuild_kernel<<<256, 256>>>(pG, pm, pE, pSlots, pNxt, pCcat, pZc);
    vcat_kernel<<<512, 512>>>(pV, MV, pSlots, pVcat);
    gemm_kernel<false><<<dim3(4, 2, 8), thr>>>(pCcat, pVcat, pPart, 256, 512, 512, 64);
    reduce_kernel<<<512, 256>>>(pPart, pRc, nullptr, 256*512, 512, 8, 0);

    merged_kernel<<<256, 512>>>(S, pR0, pRc, pZ0, pZc, pMg);

    // batched MLP
    gemm_kernel<true><<<dim3(16, 2, 8), thr>>>(pMg, W1, pPart, 256, 2048, 1024, 128);
    reduce_kernel<<<2048, 256>>>(pPart, pHid, b1, 256*2048, 2048, 8, 1);
    gemm_kernel<true><<<dim3(4, 2, 32), thr>>>(pHid, W2, pPart, 256, 512, 2048, 64);
    reduce_kernel<<<512, 256>>>(pPart, out, b2, 256*512, 512, 32, 0);
}